// round 6
// baseline (speedup 1.0000x reference)
#include <cuda_runtime.h>
#include <cuda_fp16.h>
#include <cuda_bf16.h>
#include <cstdint>

#define BB 16
#define N1 4096
#define N2 1024
#define C1 128
#define C2 256
#define DIN 384
#define DOUT 256
#define NQ (BB * N1)

// ---------------- device scratch ----------------
__device__ __align__(16) int    g_idx[NQ * 3];
__device__ __align__(16) float  g_w[NQ * 3];
__device__ __align__(16) __half g_X[(size_t)NQ * DIN];
__device__ __align__(16) __half g_W1T[DOUT * DIN];
__device__ __align__(16) __half g_W2T[DOUT * DOUT];
__device__ __align__(16) __half g_feat2h[(size_t)BB * N2 * C2];

// ---------------- PTX helpers (portable, OK on compute_103) ----------------
__device__ __forceinline__ uint32_t smem_u32(const void* p) {
    uint32_t a;
    asm("{ .reg .u64 t; cvta.to.shared.u64 t, %1; cvt.u32.u64 %0, t; }" : "=r"(a) : "l"(p));
    return a;
}
#define CP_ASYNC16(dst, src) \
    asm volatile("cp.async.cg.shared.global [%0], [%1], 16;" :: "r"(dst), "l"(src))
#define CP_COMMIT() asm volatile("cp.async.commit_group;" ::: "memory")
#define CP_WAIT(n)  asm volatile("cp.async.wait_group %0;" :: "n"(n) : "memory")

__device__ __forceinline__ void ldmatrix_x4(uint32_t* r, uint32_t addr) {
    asm volatile("ldmatrix.sync.aligned.m8n8.x4.shared.b16 {%0,%1,%2,%3}, [%4];"
                 : "=r"(r[0]), "=r"(r[1]), "=r"(r[2]), "=r"(r[3]) : "r"(addr));
}
__device__ __forceinline__ void mma16816(float* d, const uint32_t* a, const uint32_t* b) {
    asm volatile(
        "mma.sync.aligned.m16n8k16.row.col.f32.f16.f16.f32 "
        "{%0,%1,%2,%3}, {%4,%5,%6,%7}, {%8,%9}, {%0,%1,%2,%3};"
        : "+f"(d[0]), "+f"(d[1]), "+f"(d[2]), "+f"(d[3])
        : "r"(a[0]), "r"(a[1]), "r"(a[2]), "r"(a[3]), "r"(b[0]), "r"(b[1]));
}
#define SWZ(bo) ((bo) ^ (((bo) >> 3) & 0x70))

// ---------------------------------------------------------------------------
// Kernel 1: exact 3-NN. float4 smem, interleaved sub-partition, shuffle merge.
// ---------------------------------------------------------------------------
__global__ __launch_bounds__(256) void knn_kernel(const float* __restrict__ xyz1,
                                                  const float* __restrict__ xyz2) {
    __shared__ float4 pts[N2];
    const int qb = blockIdx.x * 64;
    const int b = qb >> 12;
    const float* x2 = xyz2 + (size_t)b * N2 * 3;
    for (int j = threadIdx.x; j < N2; j += 256) {
        pts[j] = make_float4(x2[3 * j], x2[3 * j + 1], x2[3 * j + 2], 0.0f);
    }
    __syncthreads();

    const int q = qb + (threadIdx.x >> 2);
    const int sub = threadIdx.x & 3;
    const float qx = xyz1[3 * q], qy = xyz1[3 * q + 1], qz = xyz1[3 * q + 2];

    float b0 = 3.4e38f, b1 = 3.4e38f, b2 = 3.4e38f;
    int i0 = 0, i1 = 0, i2 = 0;
#pragma unroll 4
    for (int i = 0; i < 256; i++) {
        const int j = sub + 4 * i;
        float4 p = pts[j];
        float dx = qx - p.x, dy = qy - p.y, dz = qz - p.z;
        float d = dx * dx + dy * dy + dz * dz;
        if (d < b2) {
            if (d < b1) {
                if (d < b0) { b2 = b1; i2 = i1; b1 = b0; i1 = i0; b0 = d; i0 = j; }
                else        { b2 = b1; i2 = i1; b1 = d; i1 = j; }
            } else { b2 = d; i2 = j; }
        }
    }
#pragma unroll
    for (int dlt = 1; dlt <= 2; dlt <<= 1) {
        float c0 = __shfl_xor_sync(0xffffffffu, b0, dlt);
        float c1 = __shfl_xor_sync(0xffffffffu, b1, dlt);
        float c2 = __shfl_xor_sync(0xffffffffu, b2, dlt);
        int k0 = __shfl_xor_sync(0xffffffffu, i0, dlt);
        int k1 = __shfl_xor_sync(0xffffffffu, i1, dlt);
        int k2 = __shfl_xor_sync(0xffffffffu, i2, dlt);
        if (c0 < b0) {
            float tf; int ti;
            tf = b0; b0 = c0; c0 = tf; ti = i0; i0 = k0; k0 = ti;
            tf = b1; b1 = c1; c1 = tf; ti = i1; i1 = k1; k1 = ti;
            tf = b2; b2 = c2; c2 = tf; ti = i2; i2 = k2; k2 = ti;
        }
        if (c0 < b1) {
            if (b1 < c1) { b2 = b1; i2 = i1; } else { b2 = c1; i2 = k1; }
            b1 = c0; i1 = k0;
        } else if (c0 < b2) { b2 = c0; i2 = k0; }
        (void)c2; (void)k2;
    }
    if (sub == 0) {
        float d0 = fmaxf(b0, 1e-10f), d1 = fmaxf(b1, 1e-10f), d2 = fmaxf(b2, 1e-10f);
        float w0 = 1.0f / d0, w1 = 1.0f / d1, w2 = 1.0f / d2;
        float inv = 1.0f / (w0 + w1 + w2);
        g_idx[q * 3] = i0; g_idx[q * 3 + 1] = i1; g_idx[q * 3 + 2] = i2;
        g_w[q * 3] = w0 * inv; g_w[q * 3 + 1] = w1 * inv; g_w[q * 3 + 2] = w2 * inv;
    }
}

// ---------------------------------------------------------------------------
// Kernel 1b: convert feat2 -> fp16
// ---------------------------------------------------------------------------
__global__ void f2h_kernel(const float* __restrict__ src) {
    const size_t i = ((size_t)blockIdx.x * 256 + threadIdx.x) * 4;
    float4 v = *(const float4*)(src + i);
    __half2 h0 = __floats2half2_rn(v.x, v.y);
    __half2 h1 = __floats2half2_rn(v.z, v.w);
    uint2 o;
    o.x = *(const uint32_t*)&h0;
    o.y = *(const uint32_t*)&h1;
    *(uint2*)(g_feat2h + i) = o;
}

// ---------------------------------------------------------------------------
// Kernel 2: interpolate (fp16 gather) + concat feat1 -> X (fp16)
// ---------------------------------------------------------------------------
__device__ __forceinline__ void to_h4(float4 o, __half* p) {
    __half2 h0 = __floats2half2_rn(o.x, o.y);
    __half2 h1 = __floats2half2_rn(o.z, o.w);
    *(__half2*)p = h0; *(__half2*)(p + 2) = h1;
}

__global__ void interp_kernel(const float* __restrict__ feat1) {
    const int q = blockIdx.x * 8 + (threadIdx.x >> 5);
    const int lane = threadIdx.x & 31;
    const int b = q >> 12;
    const int i0 = g_idx[q * 3], i1 = g_idx[q * 3 + 1], i2 = g_idx[q * 3 + 2];
    const float w0 = g_w[q * 3], w1 = g_w[q * 3 + 1], w2 = g_w[q * 3 + 2];

    const __half* f2 = g_feat2h + (size_t)b * N2 * C2;
    const uint4 v0 = ((const uint4*)(f2 + (size_t)i0 * C2))[lane];
    const uint4 v1 = ((const uint4*)(f2 + (size_t)i1 * C2))[lane];
    const uint4 v2 = ((const uint4*)(f2 + (size_t)i2 * C2))[lane];

    const __half2* h0 = (const __half2*)&v0;
    const __half2* h1 = (const __half2*)&v1;
    const __half2* h2 = (const __half2*)&v2;
    uint4 ov;
    __half2* oh = (__half2*)&ov;
#pragma unroll
    for (int k = 0; k < 4; k++) {
        float2 a = __half22float2(h0[k]);
        float2 d = __half22float2(h1[k]);
        float2 e = __half22float2(h2[k]);
        float ox = w0 * a.x + w1 * d.x + w2 * e.x;
        float oy = w0 * a.y + w1 * d.y + w2 * e.y;
        oh[k] = __floats2half2_rn(ox, oy);
    }
    __half* x = g_X + (size_t)q * DIN;
    ((uint4*)x)[lane] = ov;

    float4 f = ((const float4*)(feat1 + (size_t)q * C1))[lane];
    to_h4(f, x + C2 + lane * 4);
}

// ---------------------------------------------------------------------------
// Kernel 0: transpose W -> W^T fp16
// ---------------------------------------------------------------------------
__global__ void prep_w(const float* __restrict__ W1, const float* __restrict__ W2) {
    int i = blockIdx.x * 256 + threadIdx.x;
    if (i < DIN * DOUT) {
        int k = i / DOUT, n = i % DOUT;
        g_W1T[n * DIN + k] = __float2half(W1[i]);
    } else {
        int j = i - DIN * DOUT;
        if (j < DOUT * DOUT) {
            int k = j / DOUT, n = j % DOUT;
            g_W2T[n * DOUT + k] = __float2half(W2[j]);
        }
    }
}

// ---------------------------------------------------------------------------
// Fused MLP: one CTA = 128 rows x 256 cols, 512 threads (16 warps, 64x32
// warp tiles). Phase 1: H = relu(X@W1+b1) -> SMEM (chunked+swizzled fp16).
// Phase 2: out = relu(H@W2+b2), A served from SMEM, W2 streamed.
// SMEM map: [0,64K) H (4 chunks of 16K: 128 rows x 64 halfs, SW128)
//           [64K, 64K+2*48K) phase-1 stages {A 16K + B 32K} x2
//           [64K, 64K+2*32K) phase-2 B stages (recycled)
// ---------------------------------------------------------------------------
#define H_OFF 65536
#define STAGE_STRIDE 49152
#define FUSED_SMEM (65536 + 2 * STAGE_STRIDE)   // 163840

__global__ __launch_bounds__(512, 1) void fused_mlp(
    const __half* __restrict__ X, const __half* __restrict__ W1T,
    const __half* __restrict__ W2T,
    const float* __restrict__ b1, const float* __restrict__ b2,
    float* __restrict__ out) {
    extern __shared__ char smem[];
    const uint32_t sb = smem_u32(smem);
    const int tid = threadIdx.x;
    const int w = tid >> 5, lane = tid & 31;
    const int wy = w >> 3, wx = w & 7;        // 2 x 8 warp grid -> 64x32 tiles
    const int mblk = blockIdx.x * 128;

    float acc[4][4][4];
#pragma unroll
    for (int i = 0; i < 4; i++)
#pragma unroll
        for (int j = 0; j < 4; j++)
#pragma unroll
            for (int k = 0; k < 4; k++) acc[i][j][k] = 0.0f;

    const char* Ab = (const char*)(X + (size_t)mblk * DIN);
    const char* Bb = (const char*)W1T;

    // phase-1 loader: A chunk 128x64 (16 KB), B chunk 256x64 (32 KB)
    auto issue1 = [&](int c) {
        const uint32_t a0 = sb + (uint32_t)H_OFF + (uint32_t)(c & 1) * STAGE_STRIDE;
        const uint32_t bq = a0 + 16384u;
#pragma unroll
        for (int r = 0; r < 2; r++) {
            const int i = tid + r * 512;
            const int row = i >> 3, s = i & 7;
            CP_ASYNC16(a0 + SWZ((uint32_t)(row * 128 + s * 16)),
                       Ab + (size_t)row * 768 + c * 128 + s * 16);
        }
#pragma unroll
        for (int r = 0; r < 4; r++) {
            const int i = tid + r * 512;
            const int row = i >> 3, s = i & 7;
            CP_ASYNC16(bq + SWZ((uint32_t)(row * 128 + s * 16)),
                       Bb + (size_t)row * 768 + c * 128 + s * 16);
        }
        CP_COMMIT();
    };

    // ---- phase 1 mainloop (K=384, 6 chunks) ----
    issue1(0);
#pragma unroll
    for (int c = 0; c < 6; c++) {
        if (c + 1 < 6) { issue1(c + 1); CP_WAIT(1); }
        else           { CP_WAIT(0); }
        __syncthreads();
        const uint32_t abase = sb + (uint32_t)H_OFF + (uint32_t)(c & 1) * STAGE_STRIDE;
        const uint32_t bbase = abase + 16384u;
#pragma unroll
        for (int ks = 0; ks < 4; ks++) {
            uint32_t af[4][4];
#pragma unroll
            for (int mt = 0; mt < 4; mt++) {
                const int row = wy * 64 + mt * 16 + ((lane >> 3) & 1) * 8 + (lane & 7);
                const int ch = ks * 2 + (lane >> 4);
                ldmatrix_x4(af[mt], abase + SWZ((uint32_t)(row * 128 + ch * 16)));
            }
            uint32_t bf[4][2];
#pragma unroll
            for (int p = 0; p < 2; p++) {
                const int t = lane >> 3;
                const int nrow = wx * 32 + (2 * p + (t >> 1)) * 8 + (lane & 7);
                const int ch = ks * 2 + (t & 1);
                uint32_t r[4];
                ldmatrix_x4(r, bbase + SWZ((uint32_t)(nrow * 128 + ch * 16)));
                bf[2 * p][0] = r[0]; bf[2 * p][1] = r[1];
                bf[2 * p + 1][0] = r[2]; bf[2 * p + 1][1] = r[3];
            }
#pragma unroll
            for (int mt = 0; mt < 4; mt++)
#pragma unroll
                for (int nt = 0; nt < 4; nt++)
                    mma16816(acc[mt][nt], af[mt], bf[nt]);
        }
        __syncthreads();
    }

    // phase-2 B loader: chunk 256x64 (32 KB); recycles stage space
    const char* B2 = (const char*)W2T;
    auto issue2 = [&](int c) {
        const uint32_t bq = sb + (uint32_t)H_OFF + (uint32_t)(c & 1) * 32768u;
#pragma unroll
        for (int r = 0; r < 4; r++) {
            const int i = tid + r * 512;
            const int row = i >> 3, s = i & 7;
            CP_ASYNC16(bq + SWZ((uint32_t)(row * 128 + s * 16)),
                       B2 + (size_t)row * 512 + c * 128 + s * 16);
        }
        CP_COMMIT();
    };

    // prefetch phase-2 chunk 0 while epilogue runs (stage0 already free)
    issue2(0);

    // ---- phase-1 epilogue: bias+relu -> H in SMEM (chunked SW128 fp16) ----
#pragma unroll
    for (int mt = 0; mt < 4; mt++) {
#pragma unroll
        for (int nt = 0; nt < 4; nt++) {
            const int r0 = wy * 64 + mt * 16 + (lane >> 2);
            const int col = wx * 32 + nt * 8 + 2 * (lane & 3);
            const float bz0 = b1[col], bz1 = b1[col + 1];
            float v00 = fmaxf(acc[mt][nt][0] + bz0, 0.0f);
            float v01 = fmaxf(acc[mt][nt][1] + bz1, 0.0f);
            float v10 = fmaxf(acc[mt][nt][2] + bz0, 0.0f);
            float v11 = fmaxf(acc[mt][nt][3] + bz1, 0.0f);
            const int chunk = col >> 6, co = col & 63;
            char* hb = smem + chunk * 16384;
            *(__half2*)(hb + SWZ((uint32_t)(r0 * 128 + co * 2))) = __floats2half2_rn(v00, v01);
            *(__half2*)(hb + SWZ((uint32_t)((r0 + 8) * 128 + co * 2))) = __floats2half2_rn(v10, v11);
            // reset accumulators for phase 2
            acc[mt][nt][0] = 0.0f; acc[mt][nt][1] = 0.0f;
            acc[mt][nt][2] = 0.0f; acc[mt][nt][3] = 0.0f;
        }
    }
    __syncthreads();   // H fully written before phase-2 reads

    // ---- phase 2 mainloop (K=256, 4 chunks; A = H in SMEM) ----
#pragma unroll
    for (int c = 0; c < 4; c++) {
        if (c + 1 < 4) { issue2(c + 1); CP_WAIT(1); }
        else           { CP_WAIT(0); }
        __syncthreads();
        const uint32_t abase = sb + (uint32_t)(c * 16384);
        const uint32_t bbase = sb + (uint32_t)H_OFF + (uint32_t)(c & 1) * 32768u;
#pragma unroll
        for (int ks = 0; ks < 4; ks++) {
            uint32_t af[4][4];
#pragma unroll
            for (int mt = 0; mt < 4; mt++) {
                const int row = wy * 64 + mt * 16 + ((lane >> 3) & 1) * 8 + (lane & 7);
                const int ch = ks * 2 + (lane >> 4);
                ldmatrix_x4(af[mt], abase + SWZ((uint32_t)(row * 128 + ch * 16)));
            }
            uint32_t bf[4][2];
#pragma unroll
            for (int p = 0; p < 2; p++) {
                const int t = lane >> 3;
                const int nrow = wx * 32 + (2 * p + (t >> 1)) * 8 + (lane & 7);
                const int ch = ks * 2 + (t & 1);
                uint32_t r[4];
                ldmatrix_x4(r, bbase + SWZ((uint32_t)(nrow * 128 + ch * 16)));
                bf[2 * p][0] = r[0]; bf[2 * p][1] = r[1];
                bf[2 * p + 1][0] = r[2]; bf[2 * p + 1][1] = r[3];
            }
#pragma unroll
            for (int mt = 0; mt < 4; mt++)
#pragma unroll
                for (int nt = 0; nt < 4; nt++)
                    mma16816(acc[mt][nt], af[mt], bf[nt]);
        }
        __syncthreads();
    }

    // ---- phase-2 epilogue: bias+relu -> out (f32) ----
#pragma unroll
    for (int mt = 0; mt < 4; mt++) {
#pragma unroll
        for (int nt = 0; nt < 4; nt++) {
            const int r0 = mblk + wy * 64 + mt * 16 + (lane >> 2);
            const int col = wx * 32 + nt * 8 + 2 * (lane & 3);
            const float bz0 = b2[col], bz1 = b2[col + 1];
            float2 o0, o1;
            o0.x = fmaxf(acc[mt][nt][0] + bz0, 0.0f);
            o0.y = fmaxf(acc[mt][nt][1] + bz1, 0.0f);
            o1.x = fmaxf(acc[mt][nt][2] + bz0, 0.0f);
            o1.y = fmaxf(acc[mt][nt][3] + bz1, 0.0f);
            *(float2*)(out + (size_t)r0 * 256 + col) = o0;
            *(float2*)(out + (size_t)(r0 + 8) * 256 + col) = o1;
        }
    }
}

// ---------------------------------------------------------------------------
extern "C" void kernel_launch(void* const* d_in, const int* in_sizes, int n_in,
                              void* d_out, int out_size) {
    const float* xyz1  = (const float*)d_in[0];
    const float* feat1 = (const float*)d_in[1];
    const float* xyz2  = (const float*)d_in[2];
    const float* feat2 = (const float*)d_in[3];
    const float* W1    = (const float*)d_in[4];
    const float* b1    = (const float*)d_in[5];
    const float* W2    = (const float*)d_in[6];
    const float* b2    = (const float*)d_in[7];
    float* out = (float*)d_out;

    __half *X, *W1T, *W2T;
    cudaGetSymbolAddress((void**)&X, g_X);
    cudaGetSymbolAddress((void**)&W1T, g_W1T);
    cudaGetSymbolAddress((void**)&W2T, g_W2T);

    cudaFuncSetAttribute((const void*)fused_mlp,
                         cudaFuncAttributeMaxDynamicSharedMemorySize, FUSED_SMEM);

    prep_w<<<(DIN * DOUT + DOUT * DOUT) / 256, 256>>>(W1, W2);
    f2h_kernel<<<(BB * N2 * C2) / 1024, 256>>>(feat2);
    knn_kernel<<<NQ / 64, 256>>>(xyz1, xyz2);
    interp_kernel<<<NQ / 8, 256>>>(feat1);

    fused_mlp<<<NQ / 128, 512, FUSED_SMEM>>>(X, W1T, W2T, b1, b2, out);
}

// round 7
// speedup vs baseline: 1.0033x; 1.0033x over previous
#include <cuda_runtime.h>
#include <cuda_fp16.h>
#include <cuda_bf16.h>
#include <cstdint>

#define BB 16
#define N1 4096
#define N2 1024
#define C1 128
#define C2 256
#define DIN 384
#define DOUT 256
#define NQ (BB * N1)

// ---------------- device scratch ----------------
__device__ __align__(16) __half g_X[(size_t)NQ * DIN];
__device__ __align__(16) __half g_H[(size_t)NQ * DOUT];
__device__ __align__(16) __half g_W1T[DOUT * DIN];
__device__ __align__(16) __half g_W2T[DOUT * DOUT];
__device__ __align__(16) __half g_feat2h[(size_t)BB * N2 * C2];

// ---------------- PTX helpers (portable, OK on compute_103) ----------------
__device__ __forceinline__ uint32_t smem_u32(const void* p) {
    uint32_t a;
    asm("{ .reg .u64 t; cvta.to.shared.u64 t, %1; cvt.u32.u64 %0, t; }" : "=r"(a) : "l"(p));
    return a;
}
#define CP_ASYNC16(dst, src) \
    asm volatile("cp.async.cg.shared.global [%0], [%1], 16;" :: "r"(dst), "l"(src))
#define CP_COMMIT() asm volatile("cp.async.commit_group;" ::: "memory")
#define CP_WAIT(n)  asm volatile("cp.async.wait_group %0;" :: "n"(n) : "memory")

__device__ __forceinline__ void ldmatrix_x4(uint32_t* r, uint32_t addr) {
    asm volatile("ldmatrix.sync.aligned.m8n8.x4.shared.b16 {%0,%1,%2,%3}, [%4];"
                 : "=r"(r[0]), "=r"(r[1]), "=r"(r[2]), "=r"(r[3]) : "r"(addr));
}
__device__ __forceinline__ void mma16816(float* d, const uint32_t* a, const uint32_t* b) {
    asm volatile(
        "mma.sync.aligned.m16n8k16.row.col.f32.f16.f16.f32 "
        "{%0,%1,%2,%3}, {%4,%5,%6,%7}, {%8,%9}, {%0,%1,%2,%3};"
        : "+f"(d[0]), "+f"(d[1]), "+f"(d[2]), "+f"(d[3])
        : "r"(a[0]), "r"(a[1]), "r"(a[2]), "r"(a[3]), "r"(b[0]), "r"(b[1]));
}
#define SWZ(bo) ((bo) ^ (((bo) >> 3) & 0x70))

// ---------------------------------------------------------------------------
// Kernel A: fused 3-NN + interpolation + concat. One block = 64 queries.
// Phase 1: exact knn (4 threads/query, conflict-free float4 smem, shuffle
// merge) -> idx/w in smem. Phase 2: warp-per-query fp16 gather -> X.
// ---------------------------------------------------------------------------
__global__ __launch_bounds__(256) void knn_interp_kernel(
    const float* __restrict__ xyz1, const float* __restrict__ xyz2,
    const float* __restrict__ feat1) {
    __shared__ float4 pts[N2];
    __shared__ int   sidx[64 * 3];
    __shared__ float swt[64 * 3];

    const int qb = blockIdx.x * 64;
    const int b = qb >> 12;
    const float* x2 = xyz2 + (size_t)b * N2 * 3;
    for (int j = threadIdx.x; j < N2; j += 256) {
        pts[j] = make_float4(x2[3 * j], x2[3 * j + 1], x2[3 * j + 2], 0.0f);
    }
    __syncthreads();

    // ---- phase 1: knn ----
    {
        const int lq = threadIdx.x >> 2;
        const int q = qb + lq;
        const int sub = threadIdx.x & 3;
        const float qx = xyz1[3 * q], qy = xyz1[3 * q + 1], qz = xyz1[3 * q + 2];

        float b0 = 3.4e38f, b1 = 3.4e38f, b2 = 3.4e38f;
        int i0 = 0, i1 = 0, i2 = 0;
#pragma unroll 4
        for (int i = 0; i < 256; i++) {
            const int j = sub + 4 * i;
            float4 p = pts[j];
            float dx = qx - p.x, dy = qy - p.y, dz = qz - p.z;
            float d = dx * dx + dy * dy + dz * dz;
            if (d < b2) {
                if (d < b1) {
                    if (d < b0) { b2 = b1; i2 = i1; b1 = b0; i1 = i0; b0 = d; i0 = j; }
                    else        { b2 = b1; i2 = i1; b1 = d; i1 = j; }
                } else { b2 = d; i2 = j; }
            }
        }
#pragma unroll
        for (int dlt = 1; dlt <= 2; dlt <<= 1) {
            float c0 = __shfl_xor_sync(0xffffffffu, b0, dlt);
            float c1 = __shfl_xor_sync(0xffffffffu, b1, dlt);
            float c2 = __shfl_xor_sync(0xffffffffu, b2, dlt);
            int k0 = __shfl_xor_sync(0xffffffffu, i0, dlt);
            int k1 = __shfl_xor_sync(0xffffffffu, i1, dlt);
            int k2 = __shfl_xor_sync(0xffffffffu, i2, dlt);
            if (c0 < b0) {   // full triple swap keeps b-triple sorted
                float tf; int ti;
                tf = b0; b0 = c0; c0 = tf; ti = i0; i0 = k0; k0 = ti;
                tf = b1; b1 = c1; c1 = tf; ti = i1; i1 = k1; k1 = ti;
                tf = b2; b2 = c2; c2 = tf; ti = i2; i2 = k2; k2 = ti;
            }
            if (c0 < b1) {
                if (b1 < c1) { b2 = b1; i2 = i1; } else { b2 = c1; i2 = k1; }
                b1 = c0; i1 = k0;
            } else if (c0 < b2) { b2 = c0; i2 = k0; }
            (void)c2; (void)k2;
        }
        if (sub == 0) {
            float d0 = fmaxf(b0, 1e-10f), d1 = fmaxf(b1, 1e-10f), d2 = fmaxf(b2, 1e-10f);
            float w0 = 1.0f / d0, w1 = 1.0f / d1, w2 = 1.0f / d2;
            float inv = 1.0f / (w0 + w1 + w2);
            sidx[lq * 3] = i0; sidx[lq * 3 + 1] = i1; sidx[lq * 3 + 2] = i2;
            swt[lq * 3] = w0 * inv; swt[lq * 3 + 1] = w1 * inv; swt[lq * 3 + 2] = w2 * inv;
        }
    }
    __syncthreads();

    // ---- phase 2: gather + concat (warp per query, 8 iterations) ----
    const int wq = threadIdx.x >> 5;
    const int lane = threadIdx.x & 31;
    const __half* f2 = g_feat2h + (size_t)b * N2 * C2;
#pragma unroll
    for (int it = 0; it < 8; it++) {
        const int lq = it * 8 + wq;
        const int q = qb + lq;
        const int i0 = sidx[lq * 3], i1 = sidx[lq * 3 + 1], i2 = sidx[lq * 3 + 2];
        const float w0 = swt[lq * 3], w1 = swt[lq * 3 + 1], w2 = swt[lq * 3 + 2];

        const uint4 v0 = ((const uint4*)(f2 + (size_t)i0 * C2))[lane];
        const uint4 v1 = ((const uint4*)(f2 + (size_t)i1 * C2))[lane];
        const uint4 v2 = ((const uint4*)(f2 + (size_t)i2 * C2))[lane];
        const __half2* h0 = (const __half2*)&v0;
        const __half2* h1 = (const __half2*)&v1;
        const __half2* h2 = (const __half2*)&v2;
        uint4 ov;
        __half2* oh = (__half2*)&ov;
#pragma unroll
        for (int k = 0; k < 4; k++) {
            float2 a = __half22float2(h0[k]);
            float2 d = __half22float2(h1[k]);
            float2 e = __half22float2(h2[k]);
            oh[k] = __floats2half2_rn(w0 * a.x + w1 * d.x + w2 * e.x,
                                      w0 * a.y + w1 * d.y + w2 * e.y);
        }
        __half* x = g_X + (size_t)q * DIN;
        ((uint4*)x)[lane] = ov;

        float4 f = ((const float4*)(feat1 + (size_t)q * C1))[lane];
        __half2 f0 = __floats2half2_rn(f.x, f.y);
        __half2 f1h = __floats2half2_rn(f.z, f.w);
        *(__half2*)(x + C2 + lane * 4) = f0;
        *(__half2*)(x + C2 + lane * 4 + 2) = f1h;
    }
}

// ---------------------------------------------------------------------------
// Kernel B: feat2 -> fp16 AND W1/W2 transpose+fp16, one launch.
// Blocks [0, 4096): f2h. Blocks [4096, 4736): prep_w.
// ---------------------------------------------------------------------------
#define F2H_BLOCKS 4096
#define PREPW_BLOCKS 640

__global__ void prep_all(const float* __restrict__ feat2,
                         const float* __restrict__ W1,
                         const float* __restrict__ W2) {
    if (blockIdx.x < F2H_BLOCKS) {
        const size_t i = ((size_t)blockIdx.x * 256 + threadIdx.x) * 4;
        float4 v = *(const float4*)(feat2 + i);
        __half2 h0 = __floats2half2_rn(v.x, v.y);
        __half2 h1 = __floats2half2_rn(v.z, v.w);
        uint2 o;
        o.x = *(const uint32_t*)&h0;
        o.y = *(const uint32_t*)&h1;
        *(uint2*)(g_feat2h + i) = o;
    } else {
        int i = (blockIdx.x - F2H_BLOCKS) * 256 + threadIdx.x;
        if (i < DIN * DOUT) {
            int k = i / DOUT, n = i % DOUT;
            g_W1T[n * DIN + k] = __float2half(W1[i]);
        } else {
            int j = i - DIN * DOUT;
            int k = j / DOUT, n = j % DOUT;
            g_W2T[n * DOUT + k] = __float2half(W2[j]);
        }
    }
}

// ---------------------------------------------------------------------------
// HGEMM: C[M,256] = relu(A[M,K] @ W + bias). CTA tile 128x128, BK=64,
// THREE-stage cp.async pipeline, ONE __syncthreads per chunk
// (wait -> sync -> compute -> issue c+2), ldmatrix + mma.sync, f32 accum.
// ---------------------------------------------------------------------------
#define HGEMM_SMEM (3 * 32768)

template<int K, bool WRITE_H>
__global__ __launch_bounds__(256, 2) void hgemm(
    const __half* __restrict__ A, const __half* __restrict__ Bt,
    const float* __restrict__ bias,
    __half* __restrict__ outH, float* __restrict__ outF) {
    constexpr int NC = K / 64;
    extern __shared__ char smem[];
    const uint32_t sb = smem_u32(smem);
    const int tid = threadIdx.x;
    const int w = tid >> 5, lane = tid & 31;
    const int wy = w >> 2, wx = w & 3;
    const int mblk = blockIdx.y * 128, nblk = blockIdx.x * 128;

    const char* Abase = (const char*)(A + (size_t)mblk * K);
    const char* Bbase = (const char*)(Bt + (size_t)nblk * K);
    const int row_l = tid >> 3;
    const int ch_l = tid & 7;

    float acc[4][4][4];
#pragma unroll
    for (int i = 0; i < 4; i++)
#pragma unroll
        for (int j = 0; j < 4; j++)
#pragma unroll
            for (int k = 0; k < 4; k++) acc[i][j][k] = 0.0f;

    auto issue = [&](int c) {
        const uint32_t base = sb + (uint32_t)(c % 3) * 32768u;
        const char* ag = Abase + (size_t)c * 128;
        const char* bg = Bbase + (size_t)c * 128;
#pragma unroll
        for (int rr = 0; rr < 4; rr++) {
            const int row = row_l + rr * 32;
            const uint32_t off = (uint32_t)(row * 128 + ch_l * 16);
            const uint32_t d = base + SWZ(off);
            CP_ASYNC16(d, ag + (size_t)row * (K * 2) + ch_l * 16);
            CP_ASYNC16(d + 16384, bg + (size_t)row * (K * 2) + ch_l * 16);
        }
        CP_COMMIT();
    };

    issue(0);
    issue(1);
#pragma unroll
    for (int c = 0; c < NC; c++) {
        if (c + 1 < NC) { CP_WAIT(1); } else { CP_WAIT(0); }
        __syncthreads();
        const uint32_t abase = sb + (uint32_t)(c % 3) * 32768u;
        const uint32_t bbase = abase + 16384u;
#pragma unroll
        for (int ks = 0; ks < 4; ks++) {
            uint32_t af[4][4];
#pragma unroll
            for (int mt = 0; mt < 4; mt++) {
                const int row = wy * 64 + mt * 16 + ((lane >> 3) & 1) * 8 + (lane & 7);
                const int ch = ks * 2 + (lane >> 4);
                ldmatrix_x4(af[mt], abase + SWZ((uint32_t)(row * 128 + ch * 16)));
            }
            uint32_t bf[4][2];
#pragma unroll
            for (int p = 0; p < 2; p++) {
                const int t = lane >> 3;
                const int nrow = wx * 32 + (2 * p + (t >> 1)) * 8 + (lane & 7);
                const int ch = ks * 2 + (t & 1);
                uint32_t r[4];
                ldmatrix_x4(r, bbase + SWZ((uint32_t)(nrow * 128 + ch * 16)));
                bf[2 * p][0] = r[0]; bf[2 * p][1] = r[1];
                bf[2 * p + 1][0] = r[2]; bf[2 * p + 1][1] = r[3];
            }
#pragma unroll
            for (int mt = 0; mt < 4; mt++)
#pragma unroll
                for (int nt = 0; nt < 4; nt++)
                    mma16816(acc[mt][nt], af[mt], bf[nt]);
        }
        if (c + 2 < NC) issue(c + 2);
    }

#pragma unroll
    for (int mt = 0; mt < 4; mt++) {
#pragma unroll
        for (int nt = 0; nt < 4; nt++) {
            const int row0 = mblk + wy * 64 + mt * 16 + (lane >> 2);
            const int col = nblk + wx * 32 + nt * 8 + 2 * (lane & 3);
            const float bz0 = bias[col], bz1 = bias[col + 1];
            float v00 = fmaxf(acc[mt][nt][0] + bz0, 0.0f);
            float v01 = fmaxf(acc[mt][nt][1] + bz1, 0.0f);
            float v10 = fmaxf(acc[mt][nt][2] + bz0, 0.0f);
            float v11 = fmaxf(acc[mt][nt][3] + bz1, 0.0f);
            if constexpr (WRITE_H) {
                *(__half2*)(outH + (size_t)row0 * 256 + col) = __floats2half2_rn(v00, v01);
                *(__half2*)(outH + (size_t)(row0 + 8) * 256 + col) = __floats2half2_rn(v10, v11);
            } else {
                float2 o0; o0.x = v00; o0.y = v01;
                float2 o1; o1.x = v10; o1.y = v11;
                *(float2*)(outF + (size_t)row0 * 256 + col) = o0;
                *(float2*)(outF + (size_t)(row0 + 8) * 256 + col) = o1;
            }
        }
    }
}

// ---------------------------------------------------------------------------
extern "C" void kernel_launch(void* const* d_in, const int* in_sizes, int n_in,
                              void* d_out, int out_size) {
    const float* xyz1  = (const float*)d_in[0];
    const float* feat1 = (const float*)d_in[1];
    const float* xyz2  = (const float*)d_in[2];
    const float* feat2 = (const float*)d_in[3];
    const float* W1    = (const float*)d_in[4];
    const float* b1    = (const float*)d_in[5];
    const float* W2    = (const float*)d_in[6];
    const float* b2    = (const float*)d_in[7];
    float* out = (float*)d_out;

    __half *X, *H, *W1T, *W2T;
    cudaGetSymbolAddress((void**)&X, g_X);
    cudaGetSymbolAddress((void**)&H, g_H);
    cudaGetSymbolAddress((void**)&W1T, g_W1T);
    cudaGetSymbolAddress((void**)&W2T, g_W2T);

    cudaFuncSetAttribute((const void*)hgemm<DIN, true>,
                         cudaFuncAttributeMaxDynamicSharedMemorySize, HGEMM_SMEM);
    cudaFuncSetAttribute((const void*)hgemm<DOUT, false>,
                         cudaFuncAttributeMaxDynamicSharedMemorySize, HGEMM_SMEM);

    prep_all<<<F2H_BLOCKS + PREPW_BLOCKS, 256>>>(feat2, W1, W2);
    knn_interp_kernel<<<NQ / 64, 256>>>(xyz1, xyz2, feat1);

    dim3 grid(DOUT / 128, NQ / 128);
    hgemm<DIN, true><<<grid, 256, HGEMM_SMEM>>>(X, W1T, b1, H, nullptr);
    hgemm<DOUT, false><<<grid, 256, HGEMM_SMEM>>>(H, W2T, b2, nullptr, out);
}

// round 8
// speedup vs baseline: 1.0455x; 1.0421x over previous
#include <cuda_runtime.h>
#include <cuda_fp16.h>
#include <cuda_bf16.h>
#include <cstdint>

#define BB 16
#define N1 4096
#define N2 1024
#define C1 128
#define C2 256
#define DIN 384
#define DOUT 256
#define NQ (BB * N1)

// ---------------- device scratch ----------------
__device__ __align__(16) __half g_X[(size_t)NQ * DIN];
__device__ __align__(16) __half g_H[(size_t)NQ * DOUT];
__device__ __align__(16) __half g_W1T[DOUT * DIN];
__device__ __align__(16) __half g_W2T[DOUT * DOUT];
__device__ __align__(16) __half g_feat2h[(size_t)BB * N2 * C2];

// ---------------- PTX helpers (portable, OK on compute_103) ----------------
__device__ __forceinline__ uint32_t smem_u32(const void* p) {
    uint32_t a;
    asm("{ .reg .u64 t; cvta.to.shared.u64 t, %1; cvt.u32.u64 %0, t; }" : "=r"(a) : "l"(p));
    return a;
}
#define CP_ASYNC16(dst, src) \
    asm volatile("cp.async.cg.shared.global [%0], [%1], 16;" :: "r"(dst), "l"(src))
#define CP_COMMIT() asm volatile("cp.async.commit_group;" ::: "memory")
#define CP_WAIT(n)  asm volatile("cp.async.wait_group %0;" :: "n"(n) : "memory")

__device__ __forceinline__ void ldmatrix_x4(uint32_t* r, uint32_t addr) {
    asm volatile("ldmatrix.sync.aligned.m8n8.x4.shared.b16 {%0,%1,%2,%3}, [%4];"
                 : "=r"(r[0]), "=r"(r[1]), "=r"(r[2]), "=r"(r[3]) : "r"(addr));
}
__device__ __forceinline__ void mma16816(float* d, const uint32_t* a, const uint32_t* b) {
    asm volatile(
        "mma.sync.aligned.m16n8k16.row.col.f32.f16.f16.f32 "
        "{%0,%1,%2,%3}, {%4,%5,%6,%7}, {%8,%9}, {%0,%1,%2,%3};"
        : "+f"(d[0]), "+f"(d[1]), "+f"(d[2]), "+f"(d[3])
        : "r"(a[0]), "r"(a[1]), "r"(a[2]), "r"(a[3]), "r"(b[0]), "r"(b[1]));
}
#define SWZ(bo) ((bo) ^ (((bo) >> 3) & 0x70))

// ---------------------------------------------------------------------------
// Kernel A: fused 3-NN + interpolation + concat. One block = 64 queries.
// knn selection via val = |p|^2 - 2 q.p (3 FFMA/candidate, |p|^2 packed in
// pts.w). Winners' distances recomputed exactly ((x1-x2)^2 form) for weights.
// ---------------------------------------------------------------------------
__global__ __launch_bounds__(256) void knn_interp_kernel(
    const float* __restrict__ xyz1, const float* __restrict__ xyz2,
    const float* __restrict__ feat1) {
    __shared__ float4 pts[N2];
    __shared__ int   sidx[64 * 3];
    __shared__ float swt[64 * 3];

    const int qb = blockIdx.x * 64;
    const int b = qb >> 12;
    const float* x2 = xyz2 + (size_t)b * N2 * 3;
    for (int j = threadIdx.x; j < N2; j += 256) {
        float x = x2[3 * j], y = x2[3 * j + 1], z = x2[3 * j + 2];
        pts[j] = make_float4(x, y, z, x * x + y * y + z * z);
    }
    __syncthreads();

    // ---- phase 1: knn (selection on val; exact d only for winners) ----
    {
        const int lq = threadIdx.x >> 2;
        const int q = qb + lq;
        const int sub = threadIdx.x & 3;
        const float qx = xyz1[3 * q], qy = xyz1[3 * q + 1], qz = xyz1[3 * q + 2];
        const float ax = -2.0f * qx, ay = -2.0f * qy, az = -2.0f * qz;

        float b0 = 3.4e38f, b1 = 3.4e38f, b2 = 3.4e38f;
        int i0 = 0, i1 = 0, i2 = 0;
#pragma unroll 8
        for (int i = 0; i < 256; i++) {
            const int j = sub + 4 * i;
            float4 p = pts[j];
            float v = fmaf(ax, p.x, fmaf(ay, p.y, fmaf(az, p.z, p.w)));
            if (v < b2) {
                if (v < b1) {
                    if (v < b0) { b2 = b1; i2 = i1; b1 = b0; i1 = i0; b0 = v; i0 = j; }
                    else        { b2 = b1; i2 = i1; b1 = v; i1 = j; }
                } else { b2 = v; i2 = j; }
            }
        }
#pragma unroll
        for (int dlt = 1; dlt <= 2; dlt <<= 1) {
            float c0 = __shfl_xor_sync(0xffffffffu, b0, dlt);
            float c1 = __shfl_xor_sync(0xffffffffu, b1, dlt);
            float c2 = __shfl_xor_sync(0xffffffffu, b2, dlt);
            int k0 = __shfl_xor_sync(0xffffffffu, i0, dlt);
            int k1 = __shfl_xor_sync(0xffffffffu, i1, dlt);
            int k2 = __shfl_xor_sync(0xffffffffu, i2, dlt);
            if (c0 < b0) {   // full triple swap keeps b-triple sorted
                float tf; int ti;
                tf = b0; b0 = c0; c0 = tf; ti = i0; i0 = k0; k0 = ti;
                tf = b1; b1 = c1; c1 = tf; ti = i1; i1 = k1; k1 = ti;
                tf = b2; b2 = c2; c2 = tf; ti = i2; i2 = k2; k2 = ti;
            }
            if (c0 < b1) {
                if (b1 < c1) { b2 = b1; i2 = i1; } else { b2 = c1; i2 = k1; }
                b1 = c0; i1 = k0;
            } else if (c0 < b2) { b2 = c0; i2 = k0; }
            (void)c2; (void)k2;
        }
        if (sub == 0) {
            // exact reference-form distances for the 3 winners
            float4 p0 = pts[i0], p1 = pts[i1], p2 = pts[i2];
            float dx, dy, dz;
            dx = qx - p0.x; dy = qy - p0.y; dz = qz - p0.z;
            float d0 = fmaxf(dx * dx + dy * dy + dz * dz, 1e-10f);
            dx = qx - p1.x; dy = qy - p1.y; dz = qz - p1.z;
            float d1 = fmaxf(dx * dx + dy * dy + dz * dz, 1e-10f);
            dx = qx - p2.x; dy = qy - p2.y; dz = qz - p2.z;
            float d2 = fmaxf(dx * dx + dy * dy + dz * dz, 1e-10f);
            float w0 = 1.0f / d0, w1 = 1.0f / d1, w2 = 1.0f / d2;
            float inv = 1.0f / (w0 + w1 + w2);
            sidx[lq * 3] = i0; sidx[lq * 3 + 1] = i1; sidx[lq * 3 + 2] = i2;
            swt[lq * 3] = w0 * inv; swt[lq * 3 + 1] = w1 * inv; swt[lq * 3 + 2] = w2 * inv;
        }
    }
    __syncthreads();

    // ---- phase 2: gather + concat (warp per query, 8 iterations) ----
    const int wq = threadIdx.x >> 5;
    const int lane = threadIdx.x & 31;
    const __half* f2 = g_feat2h + (size_t)b * N2 * C2;
#pragma unroll
    for (int it = 0; it < 8; it++) {
        const int lq = it * 8 + wq;
        const int q = qb + lq;
        const int i0 = sidx[lq * 3], i1 = sidx[lq * 3 + 1], i2 = sidx[lq * 3 + 2];
        const float w0 = swt[lq * 3], w1 = swt[lq * 3 + 1], w2 = swt[lq * 3 + 2];

        const uint4 v0 = ((const uint4*)(f2 + (size_t)i0 * C2))[lane];
        const uint4 v1 = ((const uint4*)(f2 + (size_t)i1 * C2))[lane];
        const uint4 v2 = ((const uint4*)(f2 + (size_t)i2 * C2))[lane];
        const __half2* h0 = (const __half2*)&v0;
        const __half2* h1 = (const __half2*)&v1;
        const __half2* h2 = (const __half2*)&v2;
        uint4 ov;
        __half2* oh = (__half2*)&ov;
#pragma unroll
        for (int k = 0; k < 4; k++) {
            float2 a = __half22float2(h0[k]);
            float2 d = __half22float2(h1[k]);
            float2 e = __half22float2(h2[k]);
            oh[k] = __floats2half2_rn(w0 * a.x + w1 * d.x + w2 * e.x,
                                      w0 * a.y + w1 * d.y + w2 * e.y);
        }
        __half* x = g_X + (size_t)q * DIN;
        ((uint4*)x)[lane] = ov;

        float4 f = ((const float4*)(feat1 + (size_t)q * C1))[lane];
        __half2 f0 = __floats2half2_rn(f.x, f.y);
        __half2 f1h = __floats2half2_rn(f.z, f.w);
        *(__half2*)(x + C2 + lane * 4) = f0;
        *(__half2*)(x + C2 + lane * 4 + 2) = f1h;
    }
}

// ---------------------------------------------------------------------------
// Kernel B: feat2 -> fp16 AND W1/W2 transpose+fp16, one launch.
// ---------------------------------------------------------------------------
#define F2H_BLOCKS 4096
#define PREPW_BLOCKS 640

__global__ void prep_all(const float* __restrict__ feat2,
                         const float* __restrict__ W1,
                         const float* __restrict__ W2) {
    if (blockIdx.x < F2H_BLOCKS) {
        const size_t i = ((size_t)blockIdx.x * 256 + threadIdx.x) * 4;
        float4 v = *(const float4*)(feat2 + i);
        __half2 h0 = __floats2half2_rn(v.x, v.y);
        __half2 h1 = __floats2half2_rn(v.z, v.w);
        uint2 o;
        o.x = *(const uint32_t*)&h0;
        o.y = *(const uint32_t*)&h1;
        *(uint2*)(g_feat2h + i) = o;
    } else {
        int i = (blockIdx.x - F2H_BLOCKS) * 256 + threadIdx.x;
        if (i < DIN * DOUT) {
            int k = i / DOUT, n = i % DOUT;
            g_W1T[n * DIN + k] = __float2half(W1[i]);
        } else {
            int j = i - DIN * DOUT;
            int k = j / DOUT, n = j % DOUT;
            g_W2T[n * DOUT + k] = __float2half(W2[j]);
        }
    }
}

// ---------------------------------------------------------------------------
// HGEMM: C[M,256] = relu(A[M,K] @ W + bias). CTA tile 128x128, BK=64,
// 3-stage cp.async pipeline, one __syncthreads per chunk, ldmatrix + mma.sync.
// ---------------------------------------------------------------------------
#define HGEMM_SMEM (3 * 32768)

template<int K, bool WRITE_H>
__global__ __launch_bounds__(256, 2) void hgemm(
    const __half* __restrict__ A, const __half* __restrict__ Bt,
    const float* __restrict__ bias,
    __half* __restrict__ outH, float* __restrict__ outF) {
    constexpr int NC = K / 64;
    extern __shared__ char smem[];
    const uint32_t sb = smem_u32(smem);
    const int tid = threadIdx.x;
    const int w = tid >> 5, lane = tid & 31;
    const int wy = w >> 2, wx = w & 3;
    const int mblk = blockIdx.y * 128, nblk = blockIdx.x * 128;

    const char* Abase = (const char*)(A + (size_t)mblk * K);
    const char* Bbase = (const char*)(Bt + (size_t)nblk * K);
    const int row_l = tid >> 3;
    const int ch_l = tid & 7;

    float acc[4][4][4];
#pragma unroll
    for (int i = 0; i < 4; i++)
#pragma unroll
        for (int j = 0; j < 4; j++)
#pragma unroll
            for (int k = 0; k < 4; k++) acc[i][j][k] = 0.0f;

    auto issue = [&](int c) {
        const uint32_t base = sb + (uint32_t)(c % 3) * 32768u;
        const char* ag = Abase + (size_t)c * 128;
        const char* bg = Bbase + (size_t)c * 128;
#pragma unroll
        for (int rr = 0; rr < 4; rr++) {
            const int row = row_l + rr * 32;
            const uint32_t off = (uint32_t)(row * 128 + ch_l * 16);
            const uint32_t d = base + SWZ(off);
            CP_ASYNC16(d, ag + (size_t)row * (K * 2) + ch_l * 16);
            CP_ASYNC16(d + 16384, bg + (size_t)row * (K * 2) + ch_l * 16);
        }
        CP_COMMIT();
    };

    issue(0);
    issue(1);
#pragma unroll
    for (int c = 0; c < NC; c++) {
        if (c + 1 < NC) { CP_WAIT(1); } else { CP_WAIT(0); }
        __syncthreads();
        const uint32_t abase = sb + (uint32_t)(c % 3) * 32768u;
        const uint32_t bbase = abase + 16384u;
#pragma unroll
        for (int ks = 0; ks < 4; ks++) {
            uint32_t af[4][4];
#pragma unroll
            for (int mt = 0; mt < 4; mt++) {
                const int row = wy * 64 + mt * 16 + ((lane >> 3) & 1) * 8 + (lane & 7);
                const int ch = ks * 2 + (lane >> 4);
                ldmatrix_x4(af[mt], abase + SWZ((uint32_t)(row * 128 + ch * 16)));
            }
            uint32_t bf[4][2];
#pragma unroll
            for (int p = 0; p < 2; p++) {
                const int t = lane >> 3;
                const int nrow = wx * 32 + (2 * p + (t >> 1)) * 8 + (lane & 7);
                const int ch = ks * 2 + (t & 1);
                uint32_t r[4];
                ldmatrix_x4(r, bbase + SWZ((uint32_t)(nrow * 128 + ch * 16)));
                bf[2 * p][0] = r[0]; bf[2 * p][1] = r[1];
                bf[2 * p + 1][0] = r[2]; bf[2 * p + 1][1] = r[3];
            }
#pragma unroll
            for (int mt = 0; mt < 4; mt++)
#pragma unroll
                for (int nt = 0; nt < 4; nt++)
                    mma16816(acc[mt][nt], af[mt], bf[nt]);
        }
        if (c + 2 < NC) issue(c + 2);
    }

#pragma unroll
    for (int mt = 0; mt < 4; mt++) {
#pragma unroll
        for (int nt = 0; nt < 4; nt++) {
            const int row0 = mblk + wy * 64 + mt * 16 + (lane >> 2);
            const int col = nblk + wx * 32 + nt * 8 + 2 * (lane & 3);
            const float bz0 = bias[col], bz1 = bias[col + 1];
            float v00 = fmaxf(acc[mt][nt][0] + bz0, 0.0f);
            float v01 = fmaxf(acc[mt][nt][1] + bz1, 0.0f);
            float v10 = fmaxf(acc[mt][nt][2] + bz0, 0.0f);
            float v11 = fmaxf(acc[mt][nt][3] + bz1, 0.0f);
            if constexpr (WRITE_H) {
                *(__half2*)(outH + (size_t)row0 * 256 + col) = __floats2half2_rn(v00, v01);
                *(__half2*)(outH + (size_t)(row0 + 8) * 256 + col) = __floats2half2_rn(v10, v11);
            } else {
                float2 o0; o0.x = v00; o0.y = v01;
                float2 o1; o1.x = v10; o1.y = v11;
                *(float2*)(outF + (size_t)row0 * 256 + col) = o0;
                *(float2*)(outF + (size_t)(row0 + 8) * 256 + col) = o1;
            }
        }
    }
}

// ---------------------------------------------------------------------------
extern "C" void kernel_launch(void* const* d_in, const int* in_sizes, int n_in,
                              void* d_out, int out_size) {
    const float* xyz1  = (const float*)d_in[0];
    const float* feat1 = (const float*)d_in[1];
    const float* xyz2  = (const float*)d_in[2];
    const float* feat2 = (const float*)d_in[3];
    const float* W1    = (const float*)d_in[4];
    const float* b1    = (const float*)d_in[5];
    const float* W2    = (const float*)d_in[6];
    const float* b2    = (const float*)d_in[7];
    float* out = (float*)d_out;

    __half *X, *H, *W1T, *W2T;
    cudaGetSymbolAddress((void**)&X, g_X);
    cudaGetSymbolAddress((void**)&H, g_H);
    cudaGetSymbolAddress((void**)&W1T, g_W1T);
    cudaGetSymbolAddress((void**)&W2T, g_W2T);

    cudaFuncSetAttribute((const void*)hgemm<DIN, true>,
                         cudaFuncAttributeMaxDynamicSharedMemorySize, HGEMM_SMEM);
    cudaFuncSetAttribute((const void*)hgemm<DOUT, false>,
                         cudaFuncAttributeMaxDynamicSharedMemorySize, HGEMM_SMEM);

    prep_all<<<F2H_BLOCKS + PREPW_BLOCKS, 256>>>(feat2, W1, W2);
    knn_interp_kernel<<<NQ / 64, 256>>>(xyz1, xyz2, feat1);

    dim3 grid(DOUT / 128, NQ / 128);
    hgemm<DIN, true><<<grid, 256, HGEMM_SMEM>>>(X, W1T, b1, H, nullptr);
    hgemm<DOUT, false><<<grid, 256, HGEMM_SMEM>>>(H, W2T, b2, nullptr, out);
}